// round 4
// baseline (speedup 1.0000x reference)
#include <cuda_runtime.h>
#include <cstdint>

// ---------------- problem constants ----------------
#define NNODES 100000
#define NEDGES 1600000
#define DIN 128
#define H1 128
#define H2 64
#define NEG_SLOPE 0.2f

// ---------------- device scratch (no allocations allowed) ----------------
static __device__ __align__(16) float g_xl[(size_t)NNODES * 128];  // current layer xl
static __device__ __align__(16) float g_h1[(size_t)NNODES * 128];  // layer-1 output
static __device__ float    g_asrc[NNODES];
static __device__ float    g_adst[NNODES];
static __device__ float    g_loopsum[NNODES];
static __device__ float    g_loopattr[NNODES];
static __device__ int      g_cnt[NNODES];       // in-degree
static __device__ int      g_rowstart[NNODES];  // CSR row offsets
static __device__ int      g_fill[NNODES];      // fill cursors
static __device__ int      g_bsum[1024];        // scan block sums
static __device__ int      g_src32[NEDGES];     // converted src indices
static __device__ int      g_dst32[NEDGES];     // converted dst indices
static __device__ int      g_esrc[NEDGES];      // CSR: src node per slot
static __device__ float    g_eea[NEDGES];       // CSR: edge_attr per slot
static __device__ float    g_c[2];              // dot(W_edge, att_edge) per layer
static __device__ int      g_is64;              // edge_index dtype flag

// ---------------- helpers ----------------
__device__ __forceinline__ float leaky(float x) {
    return x >= 0.f ? x : NEG_SLOPE * x;
}
__device__ __forceinline__ int clampi(int v, int lo, int hi) {
    return v < lo ? lo : (v > hi ? hi : v);
}

// ---------------- detect edge_index dtype (int64 vs int32) ----------------
// int64 little-endian with values < 2^31: all odd 32-bit words are 0.
__global__ void detect_dtype(const int* __restrict__ w) {
    int any = 0;
    for (int k = threadIdx.x; k < 512; k += 32) any |= w[2 * k + 1];
    #pragma unroll
    for (int o = 16; o; o >>= 1) any |= __shfl_down_sync(0xFFFFFFFFu, any, o);
    if (threadIdx.x == 0) g_is64 = (any == 0) ? 1 : 0;
}

// ---------------- convert edge_index -> clamped int32 arrays ----------------
__global__ void conv_edges(const int* __restrict__ w, int E, int N) {
    int e = blockIdx.x * blockDim.x + threadIdx.x;
    if (e >= E) return;
    int s, d;
    if (g_is64) {
        s = w[2 * (size_t)e];
        d = w[2 * ((size_t)E + e)];
    } else {
        s = w[e];
        d = w[(size_t)E + e];
    }
    g_src32[e] = clampi(s, 0, N - 1);
    g_dst32[e] = clampi(d, 0, N - 1);
}

// ---------------- prep: zero counters ----------------
__global__ void zero_prep(int n) {
    int i = blockIdx.x * blockDim.x + threadIdx.x;
    if (i < n) { g_cnt[i] = 0; g_fill[i] = 0; g_loopsum[i] = 0.f; }
}

// ---------------- histogram: in-degree + loop attr sum ----------------
__global__ void hist_deg(const float* __restrict__ ea, int E) {
    int e = blockIdx.x * blockDim.x + threadIdx.x;
    if (e >= E) return;
    int d = g_dst32[e];
    atomicAdd(&g_cnt[d], 1);
    atomicAdd(&g_loopsum[d], ea[e]);
}

// ---------------- loop attr = loopsum / max(deg,1) ----------------
__global__ void node_loopattr(int n) {
    int i = blockIdx.x * blockDim.x + threadIdx.x;
    if (i < n) g_loopattr[i] = g_loopsum[i] / fmaxf((float)g_cnt[i], 1.f);
}

// ---------------- 3-kernel exclusive scan of g_cnt -> g_rowstart ----------------
__global__ void scan1(int n) {
    __shared__ int s[256];
    int t = threadIdx.x;
    int i = blockIdx.x * 256 + t;
    int v = (i < n) ? g_cnt[i] : 0;
    s[t] = v;
    __syncthreads();
    #pragma unroll
    for (int o = 1; o < 256; o <<= 1) {
        int y = (t >= o) ? s[t - o] : 0;
        __syncthreads();
        s[t] += y;
        __syncthreads();
    }
    if (i < n) g_rowstart[i] = s[t] - v;   // exclusive
    if (t == 255) g_bsum[blockIdx.x] = s[255];
}
__global__ void scan2(int nb) {
    __shared__ int s[1024];
    int t = threadIdx.x;
    int v = (t < nb) ? g_bsum[t] : 0;
    s[t] = v;
    __syncthreads();
    #pragma unroll
    for (int o = 1; o < 1024; o <<= 1) {
        int y = (t >= o) ? s[t - o] : 0;
        __syncthreads();
        s[t] += y;
        __syncthreads();
    }
    if (t < nb) g_bsum[t] = s[t] - v;      // exclusive block offsets
}
__global__ void scan3(int n) {
    int i = blockIdx.x * blockDim.x + threadIdx.x;
    if (i < n) g_rowstart[i] += g_bsum[i >> 8];
}

// ---------------- CSR fill ----------------
__global__ void csr_fill(const float* __restrict__ ea, int E) {
    int e = blockIdx.x * blockDim.x + threadIdx.x;
    if (e >= E) return;
    int s = g_src32[e];
    int d = g_dst32[e];
    int pos = g_rowstart[d] + atomicAdd(&g_fill[d], 1);
    g_esrc[pos] = s;
    g_eea[pos] = ea[e];
}

// ---------------- c = dot(W_edge, att_edge) for both layers ----------------
__global__ void calc_c_kernel(const float* __restrict__ We1, const float* __restrict__ ae1,
                              const float* __restrict__ We2, const float* __restrict__ ae2) {
    __shared__ float s1[128], s2[128];
    int t = threadIdx.x;
    s1[t] = We1[t] * ae1[t];
    s2[t] = (t < 64) ? We2[t] * ae2[t] : 0.f;
    __syncthreads();
    for (int o = 64; o; o >>= 1) {
        if (t < o) { s1[t] += s1[t + o]; s2[t] += s2[t + o]; }
        __syncthreads();
    }
    if (t == 0) { g_c[0] = s1[0]; g_c[1] = s2[0]; }
}

// ---------------- tiled FP32 GEMM: g_xl[N,Fout] = A[N,128] @ W[128,Fout] ----------------
// A_IS_H1: use g_h1 as A (layer 2); otherwise use the Ain parameter (layer 1).
template <bool A_IS_H1>
__global__ __launch_bounds__(256) void gemm128(const float* __restrict__ Ain,
                                               const float* __restrict__ W,
                                               int N, int Fout) {
    const float* A = A_IS_H1 ? (const float*)g_h1 : Ain;
    const int BM = 64, BN = 64, BK = 8;
    __shared__ float As[BK][BM];
    __shared__ float Bs[BK][BN];
    int tx = threadIdx.x & 15;
    int ty = threadIdx.x >> 4;
    int row0 = blockIdx.y * BM;
    int col0 = blockIdx.x * BN;
    float acc[4][4] = {};
    for (int kb = 0; kb < 128; kb += BK) {
        #pragma unroll
        for (int i = threadIdx.x; i < BM * BK; i += 256) {
            int m = i >> 3, k = i & 7;
            int r = row0 + m;
            As[k][m] = (r < N) ? A[(size_t)r * 128 + kb + k] : 0.f;
        }
        #pragma unroll
        for (int i = threadIdx.x; i < BK * BN; i += 256) {
            int k = i >> 6, c = i & 63;
            Bs[k][c] = W[(size_t)(kb + k) * Fout + col0 + c];
        }
        __syncthreads();
        #pragma unroll
        for (int k = 0; k < BK; k++) {
            float ra[4], rb[4];
            #pragma unroll
            for (int i = 0; i < 4; i++) ra[i] = As[k][ty * 4 + i];
            #pragma unroll
            for (int j = 0; j < 4; j++) rb[j] = Bs[k][tx * 4 + j];
            #pragma unroll
            for (int i = 0; i < 4; i++)
                #pragma unroll
                for (int j = 0; j < 4; j++)
                    acc[i][j] += ra[i] * rb[j];
        }
        __syncthreads();
    }
    #pragma unroll
    for (int i = 0; i < 4; i++) {
        int r = row0 + ty * 4 + i;
        if (r >= N) continue;
        #pragma unroll
        for (int j = 0; j < 4; j++) {
            g_xl[(size_t)r * Fout + col0 + tx * 4 + j] = acc[i][j];
        }
    }
}

// ---------------- a_src / a_dst: warp-per-node dots (reads g_xl) ----------------
template <int F>
__global__ void attdots(const float* __restrict__ atts, const float* __restrict__ attd, int N) {
    int warp = (blockIdx.x * blockDim.x + threadIdx.x) >> 5;
    int lane = threadIdx.x & 31;
    if (warp >= N) return;
    float s = 0.f, d = 0.f;
    #pragma unroll
    for (int j = lane; j < F; j += 32) {
        float v = g_xl[(size_t)warp * F + j];
        s += v * atts[j];
        d += v * attd[j];
    }
    #pragma unroll
    for (int o = 16; o; o >>= 1) {
        s += __shfl_down_sync(0xFFFFFFFFu, s, o);
        d += __shfl_down_sync(0xFFFFFFFFu, d, o);
    }
    if (lane == 0) { g_asrc[warp] = s; g_adst[warp] = d; }
}

// ---------------- fused GAT: online softmax + gather + bias + PReLU ----------------
// warp per node; lane owns F/32 consecutive floats. Reads g_xl.
// OUT_IS_H1: write g_h1 (layer 1); otherwise write the out parameter.
template <int F, bool OUT_IS_H1>
__global__ void fused_gat(const float* __restrict__ bias, const float* __restrict__ prelu_a,
                          float* __restrict__ outp, int N, int layer) {
    int w = (blockIdx.x * blockDim.x + threadIdx.x) >> 5;
    int lane = threadIdx.x & 31;
    if (w >= N) return;
    float* out = OUT_IS_H1 ? (float*)g_h1 : outp;
    constexpr int VE = F / 32;   // 4 (F=128) or 2 (F=64)
    const float c = g_c[layer];
    const float adst = g_adst[w];
    const float lself = leaky(g_asrc[w] + adst + c * g_loopattr[w]);

    float m = lself, den = 1.f;
    float acc[VE];
    {   // self-loop contribution, p_self = 1 relative to m = lself
        const float* xr = g_xl + (size_t)w * F + lane * VE;
        if (VE == 4) {
            float4 v = *(const float4*)xr;
            acc[0] = v.x; acc[1] = v.y; acc[2] = v.z; acc[3] = v.w;
        } else {
            float2 v = *(const float2*)xr;
            acc[0] = v.x; acc[1] = v.y;
        }
    }

    const int beg = g_rowstart[w];
    const int cnt = g_cnt[w];
    for (int j = 0; j < cnt; j++) {
        int   src = g_esrc[beg + j];     // same-address broadcast load
        float eav = g_eea[beg + j];
        float l = leaky(g_asrc[src] + adst + c * eav);
        float mn = fmaxf(m, l);
        float sc = __expf(m - mn);
        float p  = __expf(l - mn);
        den = den * sc + p;
        const float* sr = g_xl + (size_t)src * F + lane * VE;
        if (VE == 4) {
            float4 v = *(const float4*)sr;
            acc[0] = acc[0] * sc + p * v.x;
            acc[1] = acc[1] * sc + p * v.y;
            acc[2] = acc[2] * sc + p * v.z;
            acc[3] = acc[3] * sc + p * v.w;
        } else {
            float2 v = *(const float2*)sr;
            acc[0] = acc[0] * sc + p * v.x;
            acc[1] = acc[1] * sc + p * v.y;
        }
        m = mn;
    }

    float inv = 1.f / den;
    float a = *prelu_a;
    #pragma unroll
    for (int v = 0; v < VE; v++) {
        float o = acc[v] * inv + bias[lane * VE + v];
        out[(size_t)w * F + lane * VE + v] = o > 0.f ? o : a * o;
    }
}

extern "C" void kernel_launch(void* const* d_in, const int* in_sizes, int n_in,
                              void* d_out, int out_size) {
    const float*      x    = (const float*)d_in[0];
    const int*        eiw  = (const int*)d_in[1];   // edge_index as 32-bit words
    const float*      ea   = (const float*)d_in[2];
    const float*      W1   = (const float*)d_in[3];
    const float*      as1  = (const float*)d_in[4];
    const float*      ad1  = (const float*)d_in[5];
    const float*      We1  = (const float*)d_in[6];
    const float*      ae1  = (const float*)d_in[7];
    const float*      b1   = (const float*)d_in[8];
    const float*      W2   = (const float*)d_in[9];
    const float*      as2  = (const float*)d_in[10];
    const float*      ad2  = (const float*)d_in[11];
    const float*      We2  = (const float*)d_in[12];
    const float*      ae2  = (const float*)d_in[13];
    const float*      b2   = (const float*)d_in[14];
    const float*      pa   = (const float*)d_in[15];
    float*            out  = (float*)d_out;

    const int N = in_sizes[0] / DIN;
    const int E = in_sizes[1] / 2;

    const int TB = 256;
    int nb_N   = (N + TB - 1) / TB;       // 391 for N=100000
    int nb_E   = (E + TB - 1) / TB;
    int nb_att = ((N * 32) + TB - 1) / TB;

    // ---- shared precompute: dtype detect, edges, degree, CSR, scalar c's ----
    detect_dtype<<<1, 32>>>(eiw);
    zero_prep<<<nb_N, TB>>>(N);
    conv_edges<<<nb_E, TB>>>(eiw, E, N);
    hist_deg<<<nb_E, TB>>>(ea, E);
    node_loopattr<<<nb_N, TB>>>(N);
    scan1<<<nb_N, 256>>>(N);
    scan2<<<1, 1024>>>(nb_N);
    scan3<<<nb_N, 256>>>(N);
    csr_fill<<<nb_E, TB>>>(ea, E);
    calc_c_kernel<<<1, 128>>>(We1, ae1, We2, ae2);

    // ================= layer 1 (F = 128) =================
    {
        dim3 gg((H1 + 63) / 64, (N + 63) / 64);
        gemm128<false><<<gg, 256>>>(x, W1, N, H1);
        attdots<H1><<<nb_att, TB>>>(as1, ad1, N);
        fused_gat<H1, true><<<nb_att, TB>>>(b1, pa, out, N, 0);
    }

    // ================= layer 2 (F = 64) =================
    {
        dim3 gg((H2 + 63) / 64, (N + 63) / 64);
        gemm128<true><<<gg, 256>>>(nullptr, W2, N, H2);
        attdots<H2><<<nb_att, TB>>>(as2, ad2, N);
        fused_gat<H2, false><<<nb_att, TB>>>(b2, pa, out, N, 1);
    }
}

// round 5
// speedup vs baseline: 1.2426x; 1.2426x over previous
#include <cuda_runtime.h>
#include <cstdint>

// ---------------- problem constants ----------------
#define NNODES 100000
#define NEDGES 1600000
#define DIN 128
#define H1 128
#define H2 64
#define NEG_SLOPE 0.2f

typedef unsigned long long ull;

// ---------------- device scratch (no allocations allowed) ----------------
static __device__ __align__(16) float g_xl[(size_t)NNODES * 128];  // current layer xl
static __device__ __align__(16) float g_h1[(size_t)NNODES * 128];  // layer-1 output
static __device__ float    g_asrc[NNODES];
static __device__ float    g_adst[NNODES];
static __device__ float    g_loopsum[NNODES];
static __device__ float    g_loopattr[NNODES];
static __device__ int      g_cnt[NNODES];       // in-degree
static __device__ int      g_rowstart[NNODES];  // CSR row offsets
static __device__ int      g_fill[NNODES];      // fill cursors
static __device__ int      g_bsum[1024];        // scan block sums
static __device__ int      g_src32[NEDGES];     // converted src indices
static __device__ int      g_dst32[NEDGES];     // converted dst indices

struct __align__(8) EdgeRec { int src; float ea; };
static __device__ EdgeRec  g_epack[NEDGES];     // CSR: (src, edge_attr) per slot
static __device__ float    g_c[2];              // dot(W_edge, att_edge) per layer
static __device__ int      g_is64;              // edge_index dtype flag

// ---------------- helpers ----------------
__device__ __forceinline__ float leaky(float x) {
    return x >= 0.f ? x : NEG_SLOPE * x;
}
__device__ __forceinline__ int clampi(int v, int lo, int hi) {
    return v < lo ? lo : (v > hi ? hi : v);
}
// packed fp32x2 FMA (SASS FFMA2) — exact fp32 on both halves, 2x issue density
__device__ __forceinline__ void fma_f32x2(ull& d, ull a, ull b, ull c) {
    asm("fma.rn.f32x2 %0, %1, %2, %3;" : "=l"(d) : "l"(a), "l"(b), "l"(c));
}
__device__ __forceinline__ ull pack_dup(float x) {
    ull r;
    asm("mov.b64 %0, {%1, %1};" : "=l"(r) : "f"(x));
    return r;
}
__device__ __forceinline__ void unpack2(float& lo, float& hi, ull v) {
    asm("mov.b64 {%0, %1}, %2;" : "=f"(lo), "=f"(hi) : "l"(v));
}

// ---------------- detect edge_index dtype (int64 vs int32) ----------------
__global__ void detect_dtype(const int* __restrict__ w) {
    int any = 0;
    for (int k = threadIdx.x; k < 512; k += 32) any |= w[2 * k + 1];
    #pragma unroll
    for (int o = 16; o; o >>= 1) any |= __shfl_down_sync(0xFFFFFFFFu, any, o);
    if (threadIdx.x == 0) g_is64 = (any == 0) ? 1 : 0;
}

// ---------------- prep: zero counters ----------------
__global__ void zero_prep(int n) {
    int i = blockIdx.x * blockDim.x + threadIdx.x;
    if (i < n) { g_cnt[i] = 0; g_fill[i] = 0; g_loopsum[i] = 0.f; }
}

// ---------------- fused: edge convert + degree histogram + loop attr sum ----------------
__global__ void conv_hist(const int* __restrict__ w, const float* __restrict__ ea, int E, int N) {
    int e = blockIdx.x * blockDim.x + threadIdx.x;
    if (e >= E) return;
    int s, d;
    if (g_is64) {
        s = w[2 * (size_t)e];
        d = w[2 * ((size_t)E + e)];
    } else {
        s = w[e];
        d = w[(size_t)E + e];
    }
    s = clampi(s, 0, N - 1);
    d = clampi(d, 0, N - 1);
    g_src32[e] = s;
    g_dst32[e] = d;
    atomicAdd(&g_cnt[d], 1);
    atomicAdd(&g_loopsum[d], ea[e]);
}

// ---------------- loop attr = loopsum / max(deg,1) ----------------
__global__ void node_loopattr(int n) {
    int i = blockIdx.x * blockDim.x + threadIdx.x;
    if (i < n) g_loopattr[i] = g_loopsum[i] / fmaxf((float)g_cnt[i], 1.f);
}

// ---------------- 3-kernel exclusive scan of g_cnt -> g_rowstart ----------------
__global__ void scan1(int n) {
    __shared__ int s[256];
    int t = threadIdx.x;
    int i = blockIdx.x * 256 + t;
    int v = (i < n) ? g_cnt[i] : 0;
    s[t] = v;
    __syncthreads();
    #pragma unroll
    for (int o = 1; o < 256; o <<= 1) {
        int y = (t >= o) ? s[t - o] : 0;
        __syncthreads();
        s[t] += y;
        __syncthreads();
    }
    if (i < n) g_rowstart[i] = s[t] - v;   // exclusive
    if (t == 255) g_bsum[blockIdx.x] = s[255];
}
__global__ void scan2(int nb) {
    __shared__ int s[1024];
    int t = threadIdx.x;
    int v = (t < nb) ? g_bsum[t] : 0;
    s[t] = v;
    __syncthreads();
    #pragma unroll
    for (int o = 1; o < 1024; o <<= 1) {
        int y = (t >= o) ? s[t - o] : 0;
        __syncthreads();
        s[t] += y;
        __syncthreads();
    }
    if (t < nb) g_bsum[t] = s[t] - v;      // exclusive block offsets
}
__global__ void scan3(int n) {
    int i = blockIdx.x * blockDim.x + threadIdx.x;
    if (i < n) g_rowstart[i] += g_bsum[i >> 8];
}

// ---------------- CSR fill (packed records) ----------------
__global__ void csr_fill(const float* __restrict__ ea, int E) {
    int e = blockIdx.x * blockDim.x + threadIdx.x;
    if (e >= E) return;
    int d = g_dst32[e];
    int pos = g_rowstart[d] + atomicAdd(&g_fill[d], 1);
    EdgeRec r;
    r.src = g_src32[e];
    r.ea = ea[e];
    g_epack[pos] = r;
}

// ---------------- c = dot(W_edge, att_edge) for both layers ----------------
__global__ void calc_c_kernel(const float* __restrict__ We1, const float* __restrict__ ae1,
                              const float* __restrict__ We2, const float* __restrict__ ae2) {
    __shared__ float s1[128], s2[128];
    int t = threadIdx.x;
    s1[t] = We1[t] * ae1[t];
    s2[t] = (t < 64) ? We2[t] * ae2[t] : 0.f;
    __syncthreads();
    for (int o = 64; o; o >>= 1) {
        if (t < o) { s1[t] += s1[t + o]; s2[t] += s2[t + o]; }
        __syncthreads();
    }
    if (t == 0) { g_c[0] = s1[0]; g_c[1] = s2[0]; }
}

// ---------------- f32x2 GEMM: g_xl[N,F] = A[N,128] @ W[128,F], fused att dots ----------------
// BM=128 rows/block, BN=F (full width), BK=16. 256 threads, 8 rows x F/16 cols each.
// Epilogue also computes g_asrc/g_adst (row dot with att vectors, half-warp reduce).
template <int F, bool A_IS_H1>
__global__ __launch_bounds__(256) void gemm_f2(const float* __restrict__ Ain,
                                               const float* __restrict__ W,
                                               const float* __restrict__ atts,
                                               const float* __restrict__ attd,
                                               int N) {
    const float* A = A_IS_H1 ? (const float*)g_h1 : Ain;
    constexpr int BM = 128, BK = 16;
    constexpr int CJ = F / 16;    // cols per thread: 8 (F=128) or 4 (F=64)
    constexpr int CJ2 = CJ / 2;   // col pairs: 4 or 2
    __shared__ float As[BK][BM];
    __shared__ float Ws[BK][F];
    const int tid = threadIdx.x;
    const int tx = tid & 15;
    const int ty = tid >> 4;
    const int row0 = blockIdx.x * BM;

    ull acc[8][CJ2];
    #pragma unroll
    for (int i = 0; i < 8; i++)
        #pragma unroll
        for (int j = 0; j < CJ2; j++) acc[i][j] = 0ull;

    for (int kb = 0; kb < 128; kb += BK) {
        // stage A chunk (BM x BK), transposed: As[k][r]
        #pragma unroll
        for (int q = 0; q < 2; q++) {
            int f4 = tid * 2 + q;
            int r = f4 >> 2, c4 = f4 & 3;
            float4 v = make_float4(0.f, 0.f, 0.f, 0.f);
            if (row0 + r < N)
                v = *(const float4*)&A[(size_t)(row0 + r) * 128 + kb + c4 * 4];
            As[c4 * 4 + 0][r] = v.x;
            As[c4 * 4 + 1][r] = v.y;
            As[c4 * 4 + 2][r] = v.z;
            As[c4 * 4 + 3][r] = v.w;
        }
        // stage W chunk (BK x F), row-major
        constexpr int NF4 = BK * F / 4;            // 512 (F=128) or 256 (F=64)
        #pragma unroll
        for (int q = 0; q < NF4 / 256; q++) {
            int f4 = tid + q * 256;
            int k = f4 / (F / 4);
            int c = (f4 % (F / 4)) * 4;
            *(float4*)&Ws[k][c] = *(const float4*)&W[(size_t)(kb + k) * F + c];
        }
        __syncthreads();
        #pragma unroll
        for (int k = 0; k < BK; k++) {
            float4 a0 = *(const float4*)&As[k][ty * 8];
            float4 a1 = *(const float4*)&As[k][ty * 8 + 4];
            ull a2[8];
            a2[0] = pack_dup(a0.x); a2[1] = pack_dup(a0.y);
            a2[2] = pack_dup(a0.z); a2[3] = pack_dup(a0.w);
            a2[4] = pack_dup(a1.x); a2[5] = pack_dup(a1.y);
            a2[6] = pack_dup(a1.z); a2[7] = pack_dup(a1.w);
            ull b2[CJ2];
            #pragma unroll
            for (int j = 0; j < CJ2; j += 2) {
                ulonglong2 bv = *(const ulonglong2*)&Ws[k][tx * CJ + j * 2];
                b2[j] = bv.x;
                b2[j + 1] = bv.y;
            }
            #pragma unroll
            for (int i = 0; i < 8; i++)
                #pragma unroll
                for (int j = 0; j < CJ2; j++)
                    fma_f32x2(acc[i][j], a2[i], b2[j], acc[i][j]);
        }
        __syncthreads();
    }

    // epilogue: store C rows + fused att_src/att_dst dots
    float asv[CJ], adv[CJ];
    #pragma unroll
    for (int j = 0; j < CJ; j++) {
        asv[j] = __ldg(&atts[tx * CJ + j]);
        adv[j] = __ldg(&attd[tx * CJ + j]);
    }
    #pragma unroll
    for (int i = 0; i < 8; i++) {
        int r = row0 + ty * 8 + i;
        if (r >= N) break;
        float c8[CJ];
        #pragma unroll
        for (int j = 0; j < CJ2; j++) unpack2(c8[2 * j], c8[2 * j + 1], acc[i][j]);
        #pragma unroll
        for (int j = 0; j < CJ; j += 4) {
            float4 v = make_float4(c8[j], c8[j + 1], c8[j + 2], c8[j + 3]);
            *(float4*)&g_xl[(size_t)r * F + tx * CJ + j] = v;
        }
        float s = 0.f, d = 0.f;
        #pragma unroll
        for (int j = 0; j < CJ; j++) { s += c8[j] * asv[j]; d += c8[j] * adv[j]; }
        #pragma unroll
        for (int o = 8; o; o >>= 1) {
            s += __shfl_down_sync(0xFFFFFFFFu, s, o, 16);
            d += __shfl_down_sync(0xFFFFFFFFu, d, o, 16);
        }
        if (tx == 0) { g_asrc[r] = s; g_adst[r] = d; }
    }
}

// ---------------- fused GAT: online softmax + gather + bias + PReLU ----------------
// warp per node; lane owns F/32 consecutive floats. Reads g_xl.
template <int F, bool OUT_IS_H1>
__global__ void fused_gat(const float* __restrict__ bias, const float* __restrict__ prelu_a,
                          float* __restrict__ outp, int N, int layer) {
    int w = (blockIdx.x * blockDim.x + threadIdx.x) >> 5;
    int lane = threadIdx.x & 31;
    if (w >= N) return;
    float* out = OUT_IS_H1 ? (float*)g_h1 : outp;
    constexpr int VE = F / 32;   // 4 (F=128) or 2 (F=64)
    const float c = g_c[layer];
    const float adst = g_adst[w];
    const float lself = leaky(g_asrc[w] + adst + c * g_loopattr[w]);

    float m = lself, den = 1.f;
    float acc[VE];
    {   // self-loop contribution, p_self = 1 relative to m = lself
        const float* xr = g_xl + (size_t)w * F + lane * VE;
        if (VE == 4) {
            float4 v = *(const float4*)xr;
            acc[0] = v.x; acc[1] = v.y; acc[2] = v.z; acc[3] = v.w;
        } else {
            float2 v = *(const float2*)xr;
            acc[0] = v.x; acc[1] = v.y;
        }
    }

    const int beg = g_rowstart[w];
    const int cnt = g_cnt[w];
    for (int j = 0; j < cnt; j++) {
        EdgeRec er = g_epack[beg + j];   // 8B broadcast load (warp-uniform)
        float l = leaky(g_asrc[er.src] + adst + c * er.ea);
        const float* sr = g_xl + (size_t)er.src * F + lane * VE;
        float v[VE];
        if (VE == 4) {
            float4 t = *(const float4*)sr;
            v[0] = t.x; v[1] = t.y; v[2] = t.z; v[3] = t.w;
        } else {
            float2 t = *(const float2*)sr;
            v[0] = t.x; v[1] = t.y;
        }
        if (l <= m) {                      // common path: 1 expf, no rescale
            float p = __expf(l - m);
            den += p;
            #pragma unroll
            for (int q = 0; q < VE; q++) acc[q] += p * v[q];
        } else {                           // new max: rescale (rare, ~ln(deg) times)
            float sc = __expf(m - l);
            den = den * sc + 1.f;
            #pragma unroll
            for (int q = 0; q < VE; q++) acc[q] = acc[q] * sc + v[q];
            m = l;
        }
    }

    float inv = 1.f / den;
    float a = *prelu_a;
    #pragma unroll
    for (int q = 0; q < VE; q++) {
        float o = acc[q] * inv + bias[lane * VE + q];
        out[(size_t)w * F + lane * VE + q] = o > 0.f ? o : a * o;
    }
}

extern "C" void kernel_launch(void* const* d_in, const int* in_sizes, int n_in,
                              void* d_out, int out_size) {
    const float*      x    = (const float*)d_in[0];
    const int*        eiw  = (const int*)d_in[1];   // edge_index as 32-bit words
    const float*      ea   = (const float*)d_in[2];
    const float*      W1   = (const float*)d_in[3];
    const float*      as1  = (const float*)d_in[4];
    const float*      ad1  = (const float*)d_in[5];
    const float*      We1  = (const float*)d_in[6];
    const float*      ae1  = (const float*)d_in[7];
    const float*      b1   = (const float*)d_in[8];
    const float*      W2   = (const float*)d_in[9];
    const float*      as2  = (const float*)d_in[10];
    const float*      ad2  = (const float*)d_in[11];
    const float*      We2  = (const float*)d_in[12];
    const float*      ae2  = (const float*)d_in[13];
    const float*      b2   = (const float*)d_in[14];
    const float*      pa   = (const float*)d_in[15];
    float*            out  = (float*)d_out;

    const int N = in_sizes[0] / DIN;
    const int E = in_sizes[1] / 2;

    const int TB = 256;
    int nb_N   = (N + TB - 1) / TB;       // 391 for N=100000
    int nb_E   = (E + TB - 1) / TB;
    int nb_att = ((N * 32) + TB - 1) / TB;
    int nb_gemm = (N + 127) / 128;

    // ---- shared precompute: dtype detect, edges+degree, CSR, scalar c's ----
    detect_dtype<<<1, 32>>>(eiw);
    zero_prep<<<nb_N, TB>>>(N);
    conv_hist<<<nb_E, TB>>>(eiw, ea, E, N);
    node_loopattr<<<nb_N, TB>>>(N);
    scan1<<<nb_N, 256>>>(N);
    scan2<<<1, 1024>>>(nb_N);
    scan3<<<nb_N, 256>>>(N);
    csr_fill<<<nb_E, TB>>>(ea, E);
    calc_c_kernel<<<1, 128>>>(We1, ae1, We2, ae2);

    // ================= layer 1 (F = 128) =================
    gemm_f2<H1, false><<<nb_gemm, 256>>>(x, W1, as1, ad1, N);
    fused_gat<H1, true><<<nb_att, TB>>>(b1, pa, out, N, 0);

    // ================= layer 2 (F = 64) =================
    gemm_f2<H2, true><<<nb_gemm, 256>>>(nullptr, W2, as2, ad2, N);
    fused_gat<H2, false><<<nb_att, TB>>>(b2, pa, out, N, 1);
}